// round 15
// baseline (speedup 1.0000x reference)
#include <cuda_runtime.h>
#include <cuda_bf16.h>
#include <math.h>
#include <stdint.h>

// Problem constants
#define K_EMB   1024
#define D_EMB   256
#define N_VEC   65536          // 4 * 16 * 32 * 32
#define DHW     16384          // 16*32*32
#define ZQ_ELEMS (N_VEC * D_EMB)
#define LOSS_OFF ZQ_ELEMS
#define IDX_OFF  (ZQ_ELEMS + 1)
#define PERP_OFF (ZQ_ELEMS + 1 + N_VEC)

#define TAU 3e-3f

// ---------------------------------------------------------------------------
// Static device scratch (no runtime allocation allowed)
__device__ signed char g_z8[N_VEC * D_EMB];     // z int8, [n][d]
__device__ float       g_zT[N_VEC * D_EMB];     // z fp32 transposed, [n][d]
__device__ signed char g_e8[K_EMB * D_EMB];     // emb int8, [k][d]
__device__ float g_enorm[K_EMB];
__device__ float g_xnorm[N_VEC];
__device__ float g_eamax;                       // max |e|
__device__ int   g_zamax_bits;                  // max |z| as float bits
__device__ int   g_hist[K_EMB];
__device__ float g_partial[1024];               // per-CTA loss partials

// ---------------------------------------------------------------------------
static __device__ __forceinline__ uint32_t s2u(const void* p) {
    uint32_t a;
    asm("{ .reg .u64 t; cvta.to.shared.u64 t, %1; cvt.u32.u64 %0, t; }"
        : "=r"(a) : "l"(p));
    return a;
}
static __device__ __forceinline__ void ldsm_x4(uint32_t* r, uint32_t addr) {
    asm volatile("ldmatrix.sync.aligned.m8n8.x4.shared.b16 {%0,%1,%2,%3}, [%4];"
        : "=r"(r[0]), "=r"(r[1]), "=r"(r[2]), "=r"(r[3]) : "r"(addr));
}
// int8 MMA: m16n8k32, s8 x s8 -> s32
static __device__ __forceinline__ void mma16832_s8(int* d, const uint32_t* a,
                                                   const uint32_t* b) {
    asm volatile(
        "mma.sync.aligned.m16n8k32.row.col.s32.s8.s8.s32 "
        "{%0,%1,%2,%3}, {%4,%5,%6,%7}, {%8,%9}, {%0,%1,%2,%3};"
        : "+r"(d[0]), "+r"(d[1]), "+r"(d[2]), "+r"(d[3])
        : "r"(a[0]), "r"(a[1]), "r"(a[2]), "r"(a[3]), "r"(b[0]), "r"(b[1]));
}
#define CP_ASYNC16(s, g) \
    asm volatile("cp.async.cg.shared.global [%0], [%1], 16;" \
        :: "r"(s), "l"(g) : "memory")
#define CP_COMMIT() asm volatile("cp.async.commit_group;" ::: "memory")
#define CP_WAIT(n)  asm volatile("cp.async.wait_group %0;" :: "n"(n) : "memory")

// smem layout (bytes). int8 rows of 256B padded to 272 => LDSM conflict-free
// (272 % 128 == 16, same bank-shift property as the validated 528 pitch).
#define ROW_PITCH 272
#define SM_A     0                         // 64 x 272 = 17408 (A tile; A∪B0 later = z_q gather tile)
#define SM_B0    17408                     // 64 x 272 = 17408
#define SM_B1    34816                     // 64 x 272 = 17408
#define SM_EN    52224                     // 1024 f32 = 4096 (later loss-reduce)
#define SM_CAND  56320                     // 64*64 u16 = 8192
#define SM_CNT   64512                     // 64 u32 = 256
#define SM_IDX   64768                     // 64 s32 = 256
#define SM_TOTAL 65024
#define G_PITCH  528                       // gather tile pitch (fp32, 128 cols)

// ---------------------------------------------------------------------------
// prep (single block, 1024 threads): zero hist/zamax + enorm (sequential
// in-order fp32) + e amax (block reduce) + int8 quantize of emb.
__global__ void vq_prep_kernel(const float* __restrict__ emb) {
    __shared__ float red[1024];
    int k = threadIdx.x;
    g_hist[k] = 0;
    if (k == 0) g_zamax_bits = 0;

    const float* row = emb + (size_t)k * D_EMB;
    float acc = 0.0f, am = 0.0f;
    for (int d = 0; d < D_EMB; d++) {
        float v = row[d];
        acc = __fadd_rn(acc, __fmul_rn(v, v));
        am = fmaxf(am, fabsf(v));
    }
    g_enorm[k] = acc;

    red[k] = am;
    __syncthreads();
    #pragma unroll
    for (int s = 512; s > 0; s >>= 1) {
        if (k < s) red[k] = fmaxf(red[k], red[k + s]);
        __syncthreads();
    }
    float eamax = red[0];
    if (k == 0) g_eamax = eamax;

    float Se = 127.0f / eamax;
    signed char* e8 = g_e8 + (size_t)k * D_EMB;
    for (int d = 0; d < D_EMB; d++)
        e8[d] = (signed char)__float2int_rn(row[d] * Se);
}

// xnorm[n]: sequential in-order fp32 sum over channel dim (reference-faithful)
// + block-reduced global amax of |z|.
__global__ void vq_xnorm_kernel(const float* __restrict__ z) {
    __shared__ float red[256];
    int n = blockIdx.x * blockDim.x + threadIdx.x;
    int b = n >> 14;
    int dhw = n & 16383;
    const float* p = z + (size_t)b * D_EMB * DHW + dhw;
    float acc = 0.0f, am = 0.0f;
    for (int c = 0; c < D_EMB; c++) {
        float v = p[(size_t)c * DHW];
        acc = __fadd_rn(acc, __fmul_rn(v, v));
        am = fmaxf(am, fabsf(v));
    }
    g_xnorm[n] = acc;

    red[threadIdx.x] = am;
    __syncthreads();
    #pragma unroll
    for (int s = 128; s > 0; s >>= 1) {
        if (threadIdx.x < s) red[threadIdx.x] = fmaxf(red[threadIdx.x], red[threadIdx.x + s]);
        __syncthreads();
    }
    if (threadIdx.x == 0) atomicMax(&g_zamax_bits, __float_as_int(red[0]));
}

// transpose z (b,c,dhw) -> [n][d]: fp32 copy + int8 quantize
__global__ void vq_split_z_kernel(const float* __restrict__ z) {
    __shared__ float tile[32][33];
    int nBase = blockIdx.x * 32;
    int cBase = blockIdx.y * 32;
    int tx = threadIdx.x, ty = threadIdx.y;
    int b = nBase >> 14;
    int dhw = (nBase & 16383) + tx;
    float Sz = 127.0f / __int_as_float(g_zamax_bits);

    #pragma unroll
    for (int i = 0; i < 4; i++) {
        int cl = ty + 8 * i;
        tile[cl][tx] = z[((size_t)(b * D_EMB + cBase + cl)) * DHW + dhw];
    }
    __syncthreads();
    #pragma unroll
    for (int i = 0; i < 4; i++) {
        int nl = ty + 8 * i;
        float v = tile[tx][nl];
        int o = (nBase + nl) * D_EMB + cBase + tx;
        g_zT[o] = v;
        g_z8[o] = (signed char)__float2int_rn(v * Sz);
    }
}

// ---------------------------------------------------------------------------
// Fused: int8 mma.sync filter (2x MACs/instr vs bf16) + exact fp32 rescore +
// gather/z_q/loss/hist. CTA: 64 rows x 1024 codes, 128 threads, 2 CTAs/SM.
__global__ void __launch_bounds__(128, 2)
vq_topk_kernel(const float* __restrict__ emb, float* __restrict__ out) {
    extern __shared__ char sm[];
    uint32_t sb = s2u(sm);
    float*          sEn   = (float*)(sm + SM_EN);
    unsigned short* sCand = (unsigned short*)(sm + SM_CAND);
    unsigned int*   sCnt  = (unsigned int*)(sm + SM_CNT);
    int*            sIdx  = (int*)(sm + SM_IDX);

    int tid  = threadIdx.x;
    int wid  = tid >> 5;                    // 0..3
    int lane = tid & 31;
    int rowBase = blockIdx.x * 64;

    // combined dequant factor: dot = dot32 * (zamax/127)*(eamax/127)
    float inv2 = -2.0f * (__int_as_float(g_zamax_bits) / 127.0f)
                       * (g_eamax / 127.0f);

    // Stage A tile (cp.async): 64 rows x 256B int8 (1024 16B chunks)
    {
        const signed char* za = g_z8 + (size_t)rowBase * D_EMB;
        #pragma unroll
        for (int j = 0; j < 8; j++) {
            int i = tid + j * 128;
            int r = i >> 4, c = i & 15;
            CP_ASYNC16(sb + SM_A + r * ROW_PITCH + c * 16,
                       (const char*)(za + (size_t)r * D_EMB + c * 16));
        }
        CP_COMMIT();
    }
    // Prefetch B chunk 0 into B0
    {
        #pragma unroll
        for (int j = 0; j < 8; j++) {
            int i = tid + j * 128;
            int r = i >> 4, c = i & 15;
            CP_ASYNC16(sb + SM_B0 + r * ROW_PITCH + c * 16,
                       (const char*)(g_e8 + (size_t)r * D_EMB + c * 16));
        }
        CP_COMMIT();
    }

    if (tid < 64) sCnt[tid] = 0;
    for (int i = tid; i < K_EMB; i += 128) sEn[i] = g_enorm[i];

    CP_WAIT(1);                  // A complete
    __syncthreads();

    // A fragments: warp w owns rows 16w..16w+15; 8 k32-fragments x 4 regs.
    // Addressing identical in BYTES to the validated bf16 layout (k-tile = 32B).
    uint32_t afrag[8][4];
    {
        uint32_t base = sb + SM_A + (wid * 16 + (lane & 15)) * ROW_PITCH
                      + (lane >> 4) * 16;
        #pragma unroll
        for (int kf = 0; kf < 8; kf++) ldsm_x4(afrag[kf], base + kf * 32);
    }

    int r0loc = wid * 16 + (lane >> 2);     // row of s0/s1; s2/s3 -> r0loc+8
    float run0 = 1e30f, run1 = 1e30f;

    for (int chunk = 0; chunk < 16; chunk++) {
        uint32_t bufC = (chunk & 1) ? SM_B1 : SM_B0;
        if (chunk < 15) {
            uint32_t bufN = (chunk & 1) ? SM_B0 : SM_B1;
            const signed char* eb = g_e8 + (size_t)((chunk + 1) * 64) * D_EMB;
            #pragma unroll
            for (int j = 0; j < 8; j++) {
                int i = tid + j * 128;
                int r = i >> 4, c = i & 15;
                CP_ASYNC16(sb + bufN + r * ROW_PITCH + c * 16,
                           (const char*)(eb + (size_t)r * D_EMB + c * 16));
            }
            CP_COMMIT();
            CP_WAIT(1);          // current chunk complete
        } else {
            CP_WAIT(0);
        }
        __syncthreads();

        float sc[32];
        float m0 = 1e30f, m1 = 1e30f;

        #pragma unroll
        for (int t = 0; t < 8; t++) {
            int kb = chunk * 64 + t * 8;
            int d4a[4] = {0, 0, 0, 0};
            int d4b[4] = {0, 0, 0, 0};
            uint32_t bbase = sb + bufC + (t * 8 + (lane & 7)) * ROW_PITCH
                           + (lane >> 3) * 16;
            #pragma unroll
            for (int j = 0; j < 4; j++) {
                uint32_t bfr[4];
                ldsm_x4(bfr, bbase + j * 64);      // k bytes [64j, 64j+64)
                mma16832_s8(d4a, afrag[2 * j],     bfr);      // kf 2j
                mma16832_s8(d4b, afrag[2 * j + 1], bfr + 2);  // kf 2j+1
            }
            int c0 = kb + (lane & 3) * 2;
            float en0 = sEn[c0], en1 = sEn[c0 + 1];
            float s0 = fmaf((float)(d4a[0] + d4b[0]), inv2, en0);
            float s1 = fmaf((float)(d4a[1] + d4b[1]), inv2, en1);
            float s2 = fmaf((float)(d4a[2] + d4b[2]), inv2, en0);
            float s3 = fmaf((float)(d4a[3] + d4b[3]), inv2, en1);
            sc[2 * t] = s0; sc[2 * t + 1] = s1;
            sc[16 + 2 * t] = s2; sc[16 + 2 * t + 1] = s3;
            m0 = fminf(m0, fminf(s0, s1));
            m1 = fminf(m1, fminf(s2, s3));
        }

        // per-chunk quad reduce + running min update
        m0 = fminf(m0, __shfl_xor_sync(0xFFFFFFFFu, m0, 1));
        m0 = fminf(m0, __shfl_xor_sync(0xFFFFFFFFu, m0, 2));
        m1 = fminf(m1, __shfl_xor_sync(0xFFFFFFFFu, m1, 1));
        m1 = fminf(m1, __shfl_xor_sync(0xFFFFFFFFu, m1, 2));
        run0 = fminf(run0, m0);
        run1 = fminf(run1, m1);

        float th0 = run0 + TAU, th1 = run1 + TAU;
        #pragma unroll
        for (int j = 0; j < 16; j++) {
            int code = chunk * 64 + (j >> 1) * 8 + (lane & 3) * 2 + (j & 1);
            if (sc[j] < th0) {
                unsigned slot = atomicAdd(&sCnt[r0loc], 1u);
                if (slot < 64) sCand[r0loc * 64 + slot] = (unsigned short)code;
            }
            if (sc[16 + j] < th1) {
                unsigned slot = atomicAdd(&sCnt[r0loc + 8], 1u);
                if (slot < 64) sCand[(r0loc + 8) * 64 + slot] = (unsigned short)code;
            }
        }
        __syncthreads();         // done reading bufC before restage
    }
    __syncthreads();

    // Rescore: exact fp32 dot per candidate, reference-faithful score,
    // lexicographic (s, k) argmin. Warp w handles rows w, w+4, ...
    for (int rl = wid; rl < 64; rl += 4) {
        int n = rowBase + rl;
        float xn = g_xnorm[n];
        const float* zr = g_zT + (size_t)n * D_EMB;
        float4 za = *(const float4*)(zr + lane * 4);
        float4 zb = *(const float4*)(zr + 128 + lane * 4);

        unsigned cnt = sCnt[rl];
        int num = (cnt <= 64u) ? (int)cnt : K_EMB;
        float best = 1e30f;
        int bestk = K_EMB;
        for (int i = 0; i < num; i++) {
            int k = (cnt <= 64u) ? (int)sCand[rl * 64 + i] : i;
            const float* er = emb + (size_t)k * D_EMB;
            float4 ea = *(const float4*)(er + lane * 4);
            float4 eb4 = *(const float4*)(er + 128 + lane * 4);
            float dot = za.x * ea.x;
            dot = fmaf(za.y, ea.y, dot);
            dot = fmaf(za.z, ea.z, dot);
            dot = fmaf(za.w, ea.w, dot);
            dot = fmaf(zb.x, eb4.x, dot);
            dot = fmaf(zb.y, eb4.y, dot);
            dot = fmaf(zb.z, eb4.z, dot);
            dot = fmaf(zb.w, eb4.w, dot);
            #pragma unroll
            for (int m = 16; m > 0; m >>= 1)
                dot += __shfl_xor_sync(0xFFFFFFFFu, dot, m);
            float s = __fadd_rn(__fadd_rn(xn, sEn[k]), __fmul_rn(-2.0f, dot));
            if (s < best || (s == best && k < bestk)) { best = s; bestk = k; }
        }
        if (lane == 0) {
            sIdx[rl] = bestk;
            out[IDX_OFF + n] = (float)bestk;
            atomicAdd(&g_hist[bestk], 1);
        }
    }
    __syncthreads();

    // Fused gather: z_q in (b,c,dhw) layout + loss partial.
    // Reuses A∪B0 region (52224 B >= 64*528) as fp32 tile, pitch G_PITCH.
    int b    = rowBase >> 14;
    int dhw0 = rowBase & 16383;
    float lacc = 0.0f;
    for (int h = 0; h < 2; h++) {
        #pragma unroll
        for (int i = 0; i < 16; i++) {
            int nl = wid * 16 + i;
            int n  = rowBase + nl;
            int k  = sIdx[nl];
            float4 e4 = *(const float4*)(emb + (size_t)k * D_EMB + h * 128 + lane * 4);
            float4 z4 = *(const float4*)(g_zT + (size_t)n * D_EMB + h * 128 + lane * 4);
            *(float4*)(sm + SM_A + nl * G_PITCH + lane * 16) = e4;
            float dx = z4.x - e4.x, dy = z4.y - e4.y;
            float dz = z4.z - e4.z, dw = z4.w - e4.w;
            lacc += dx * dx + dy * dy + dz * dz + dw * dw;
        }
        __syncthreads();
        #pragma unroll
        for (int ci = 0; ci < 32; ci++) {
            int cl = wid * 32 + ci;
            #pragma unroll
            for (int i2 = 0; i2 < 2; i2++) {
                int nl = i2 * 32 + lane;
                float q = *(const float*)(sm + SM_A + nl * G_PITCH + cl * 4);
                out[((size_t)(b * D_EMB + h * 128 + cl)) * DHW + dhw0 + nl] = q;
            }
        }
        __syncthreads();
    }

    // block-reduce loss partial (deterministic tree), reuse sEn region
    float* red = sEn;
    red[tid] = lacc;
    __syncthreads();
    #pragma unroll
    for (int s = 64; s > 0; s >>= 1) {
        if (tid < s) red[tid] += red[tid + s];
        __syncthreads();
    }
    if (tid == 0) g_partial[blockIdx.x] = red[0];
}

// ---------------------------------------------------------------------------
// finalize: vq_loss (deterministic tree over 1024 partials) + perplexity
__global__ void vq_finalize_kernel(float* __restrict__ out) {
    __shared__ float red[1024];
    int t = threadIdx.x;

    red[t] = g_partial[t];
    __syncthreads();
    #pragma unroll
    for (int st = 512; st > 0; st >>= 1) {
        if (t < st) red[t] += red[t + st];
        __syncthreads();
    }
    if (t == 0) out[LOSS_OFF] = 0.25f * red[0] / (float)ZQ_ELEMS;
    __syncthreads();

    float p = (float)g_hist[t] * (1.0f / (float)N_VEC);
    red[t] = p * logf(p + 1e-10f);
    __syncthreads();
    #pragma unroll
    for (int st = 512; st > 0; st >>= 1) {
        if (t < st) red[t] += red[t + st];
        __syncthreads();
    }
    if (t == 0) out[PERP_OFF] = expf(-red[0]);
}

// ---------------------------------------------------------------------------
extern "C" void kernel_launch(void* const* d_in, const int* in_sizes, int n_in,
                              void* d_out, int out_size) {
    const float* z   = (const float*)d_in[0];
    const float* emb = (const float*)d_in[1];
    if (in_sizes[0] == K_EMB * D_EMB) {
        const float* t = z; z = emb; emb = t;
    }
    float* out = (float*)d_out;

    cudaFuncSetAttribute(vq_topk_kernel,
                         cudaFuncAttributeMaxDynamicSharedMemorySize, SM_TOTAL);

    vq_prep_kernel<<<1, 1024>>>(emb);                    // launch 1
    vq_xnorm_kernel<<<N_VEC / 256, 256>>>(z);            // launch 2

    dim3 sgrid(N_VEC / 32, D_EMB / 32);
    dim3 sblk(32, 8);
    vq_split_z_kernel<<<sgrid, sblk>>>(z);               // launch 3

    vq_topk_kernel<<<N_VEC / 64, 128, SM_TOTAL>>>(emb, out);   // launch 4 (ncu window)

    vq_finalize_kernel<<<1, 1024>>>(out);                // launch 5
}

// round 16
// speedup vs baseline: 2.5908x; 2.5908x over previous
#include <cuda_runtime.h>
#include <cuda_bf16.h>
#include <math.h>
#include <stdint.h>

// Problem constants
#define K_EMB   1024
#define D_EMB   256
#define N_VEC   65536          // 4 * 16 * 32 * 32
#define DHW     16384          // 16*32*32
#define ZQ_ELEMS (N_VEC * D_EMB)
#define LOSS_OFF ZQ_ELEMS
#define IDX_OFF  (ZQ_ELEMS + 1)
#define PERP_OFF (ZQ_ELEMS + 1 + N_VEC)

#define TAU 2e-3f

// ---------------------------------------------------------------------------
// Static device scratch (no runtime allocation allowed)
__device__ __nv_bfloat16 g_zh[N_VEC * D_EMB];   // z high bf16, [n][d]
__device__ float         g_zT[N_VEC * D_EMB];   // z fp32 transposed, [n][d]
__device__ __nv_bfloat16 g_eh[K_EMB * D_EMB];   // emb high bf16, [k][d]
__device__ float g_enorm[K_EMB];
__device__ float g_xnorm[N_VEC];
__device__ int   g_hist[K_EMB];
__device__ float g_partial[1024];               // per-CTA loss partials

// ---------------------------------------------------------------------------
static __device__ __forceinline__ uint32_t s2u(const void* p) {
    uint32_t a;
    asm("{ .reg .u64 t; cvta.to.shared.u64 t, %1; cvt.u32.u64 %0, t; }"
        : "=r"(a) : "l"(p));
    return a;
}
static __device__ __forceinline__ void ldsm_x4(uint32_t* r, uint32_t addr) {
    asm volatile("ldmatrix.sync.aligned.m8n8.x4.shared.b16 {%0,%1,%2,%3}, [%4];"
        : "=r"(r[0]), "=r"(r[1]), "=r"(r[2]), "=r"(r[3]) : "r"(addr));
}
static __device__ __forceinline__ void mma16816(float* d, const uint32_t* a,
                                                const uint32_t* b) {
    asm volatile(
        "mma.sync.aligned.m16n8k16.row.col.f32.bf16.bf16.f32 "
        "{%0,%1,%2,%3}, {%4,%5,%6,%7}, {%8,%9}, {%0,%1,%2,%3};"
        : "+f"(d[0]), "+f"(d[1]), "+f"(d[2]), "+f"(d[3])
        : "r"(a[0]), "r"(a[1]), "r"(a[2]), "r"(a[3]), "r"(b[0]), "r"(b[1]));
}
#define CP_ASYNC16(s, g) \
    asm volatile("cp.async.cg.shared.global [%0], [%1], 16;" \
        :: "r"(s), "l"(g) : "memory")
#define CP_COMMIT() asm volatile("cp.async.commit_group;" ::: "memory")
#define CP_WAIT(n)  asm volatile("cp.async.wait_group %0;" :: "n"(n) : "memory")

// smem layout (bytes). Rows padded to 528B => LDSM conflict-free (528%128==16).
// 64-row CTA: total 114176 B -> 2 CTAs/SM.
#define ROW_PITCH 528
#define SM_A     0                         // 64 x 528 = 33792 (A tile, later z_q tile)
#define SM_B0    33792                     // 64 x 528 = 33792
#define SM_B1    67584                     // 64 x 528 = 33792
#define SM_EN    101376                    // 1024 f32 = 4096 (later loss-reduce)
#define SM_CAND  105472                    // 64*64 u16 = 8192
#define SM_CNT   113664                    // 64 u32 = 256
#define SM_IDX   113920                    // 64 s32 = 256
#define SM_TOTAL 114176

// ---------------------------------------------------------------------------
// prep <<<32,256>>>: hist zero + enorm (sequential in-order fp32, via
// coalesced smem staging) + bf16 split of emb.
__global__ void vq_prep_kernel(const float* __restrict__ emb) {
    __shared__ float tile[32][257];        // pad: enorm reads conflict-free
    int tid = threadIdx.x;
    int kBase = blockIdx.x * 32;

    if (tid < 32) g_hist[kBase + tid] = 0;

    // stage 32 rows x 256 cols, coalesced
    #pragma unroll 4
    for (int j = 0; j < 32; j++)
        tile[j][tid] = emb[(size_t)(kBase + j) * D_EMB + tid];
    __syncthreads();

    // bf16 split, coalesced writes
    #pragma unroll 4
    for (int j = 0; j < 32; j++)
        g_eh[(size_t)(kBase + j) * D_EMB + tid] = __float2bfloat16(tile[j][tid]);

    // enorm: sequential in-order fp32 sum (reference-faithful); bank (t+d)%32
    if (tid < 32) {
        float acc = 0.0f;
        for (int d = 0; d < D_EMB; d++) {
            float v = tile[tid][d];
            acc = __fadd_rn(acc, __fmul_rn(v, v));
        }
        g_enorm[kBase + tid] = acc;
    }
}

// xnorm[n]: sequential in-order fp32 sum over channel dim (reference-faithful)
__global__ void vq_xnorm_kernel(const float* __restrict__ z) {
    int n = blockIdx.x * blockDim.x + threadIdx.x;
    int b = n >> 14;
    int dhw = n & 16383;
    const float* p = z + (size_t)b * D_EMB * DHW + dhw;
    float acc = 0.0f;
    for (int c = 0; c < D_EMB; c++) {
        float v = p[(size_t)c * DHW];
        acc = __fadd_rn(acc, __fmul_rn(v, v));
    }
    g_xnorm[n] = acc;
}

// transpose z (b,c,dhw) -> [n][d]: fp32 copy + bf16 high part
__global__ void vq_split_z_kernel(const float* __restrict__ z) {
    __shared__ float tile[32][33];
    int nBase = blockIdx.x * 32;
    int cBase = blockIdx.y * 32;
    int tx = threadIdx.x, ty = threadIdx.y;
    int b = nBase >> 14;
    int dhw = (nBase & 16383) + tx;

    #pragma unroll
    for (int i = 0; i < 4; i++) {
        int cl = ty + 8 * i;
        tile[cl][tx] = z[((size_t)(b * D_EMB + cBase + cl)) * DHW + dhw];
    }
    __syncthreads();
    #pragma unroll
    for (int i = 0; i < 4; i++) {
        int nl = ty + 8 * i;
        float v = tile[tx][nl];
        int o = (nBase + nl) * D_EMB + cBase + tx;
        g_zT[o] = v;
        g_zh[o] = __float2bfloat16(v);
    }
}

// ---------------------------------------------------------------------------
// Fused: bf16 mma.sync filter + exact fp32 rescore + gather/z_q/loss/hist.
// CTA: 64 rows x 1024 codes, 128 threads (4 warps) -> 2 CTAs/SM.
__global__ void __launch_bounds__(128, 2)
vq_topk_kernel(const float* __restrict__ emb, float* __restrict__ out) {
    extern __shared__ char sm[];
    uint32_t sb = s2u(sm);
    float*          sEn   = (float*)(sm + SM_EN);
    unsigned short* sCand = (unsigned short*)(sm + SM_CAND);
    unsigned int*   sCnt  = (unsigned int*)(sm + SM_CNT);
    int*            sIdx  = (int*)(sm + SM_IDX);

    int tid  = threadIdx.x;
    int wid  = tid >> 5;                    // 0..3
    int lane = tid & 31;
    int rowBase = blockIdx.x * 64;

    // Stage A tile (cp.async): 64 rows x 512B payload
    {
        const __nv_bfloat16* za = g_zh + (size_t)rowBase * D_EMB;
        #pragma unroll
        for (int j = 0; j < 16; j++) {
            int i = tid + j * 128;
            int r = i >> 5, c = i & 31;
            CP_ASYNC16(sb + SM_A + r * ROW_PITCH + c * 16,
                       (const char*)(za + (size_t)r * D_EMB + c * 8));
        }
        CP_COMMIT();
    }
    // Prefetch B chunk 0 into B0
    {
        #pragma unroll
        for (int j = 0; j < 16; j++) {
            int i = tid + j * 128;
            int r = i >> 5, c = i & 31;
            CP_ASYNC16(sb + SM_B0 + r * ROW_PITCH + c * 16,
                       (const char*)(g_eh + (size_t)r * D_EMB + c * 8));
        }
        CP_COMMIT();
    }

    if (tid < 64) sCnt[tid] = 0;
    for (int i = tid; i < K_EMB; i += 128) sEn[i] = g_enorm[i];

    CP_WAIT(1);                  // A complete
    __syncthreads();

    // A fragments: warp w owns rows 16w..16w+15; 16 k-fragments x 4 regs
    uint32_t afrag[16][4];
    {
        uint32_t base = sb + SM_A + (wid * 16 + (lane & 15)) * ROW_PITCH
                      + (lane >> 4) * 16;
        #pragma unroll
        for (int kf = 0; kf < 16; kf++) ldsm_x4(afrag[kf], base + kf * 32);
    }

    int r0loc = wid * 16 + (lane >> 2);     // row of s0/s1; s2/s3 -> r0loc+8
    float run0 = 1e30f, run1 = 1e30f;

    for (int chunk = 0; chunk < 16; chunk++) {
        uint32_t bufC = (chunk & 1) ? SM_B1 : SM_B0;
        if (chunk < 15) {
            uint32_t bufN = (chunk & 1) ? SM_B0 : SM_B1;
            const __nv_bfloat16* eb = g_eh + (size_t)((chunk + 1) * 64) * D_EMB;
            #pragma unroll
            for (int j = 0; j < 16; j++) {
                int i = tid + j * 128;
                int r = i >> 5, c = i & 31;
                CP_ASYNC16(sb + bufN + r * ROW_PITCH + c * 16,
                           (const char*)(eb + (size_t)r * D_EMB + c * 8));
            }
            CP_COMMIT();
            CP_WAIT(1);          // current chunk complete
        } else {
            CP_WAIT(0);
        }
        __syncthreads();

        float sc[32];
        float m0 = 1e30f, m1 = 1e30f;

        #pragma unroll
        for (int t = 0; t < 8; t++) {
            int kb = chunk * 64 + t * 8;
            float d4a[4] = {0.f, 0.f, 0.f, 0.f};
            float d4b[4] = {0.f, 0.f, 0.f, 0.f};
            uint32_t bbase = sb + bufC + (t * 8 + (lane & 7)) * ROW_PITCH
                           + (lane >> 3) * 16;
            uint32_t bp[4], bq[4];
            ldsm_x4(bp, bbase);
            #pragma unroll
            for (int kf2 = 0; kf2 < 8; kf2++) {
                uint32_t* bc = (kf2 & 1) ? bq : bp;
                uint32_t* bn = (kf2 & 1) ? bp : bq;
                if (kf2 < 7) ldsm_x4(bn, bbase + (kf2 + 1) * 64);
                mma16816(d4a, afrag[2 * kf2],     bc);
                mma16816(d4b, afrag[2 * kf2 + 1], bc + 2);
            }
            int c0 = kb + (lane & 3) * 2;
            float en0 = sEn[c0], en1 = sEn[c0 + 1];
            float s0 = en0 - 2.0f * (d4a[0] + d4b[0]);
            float s1 = en1 - 2.0f * (d4a[1] + d4b[1]);
            float s2 = en0 - 2.0f * (d4a[2] + d4b[2]);
            float s3 = en1 - 2.0f * (d4a[3] + d4b[3]);
            sc[2 * t] = s0; sc[2 * t + 1] = s1;
            sc[16 + 2 * t] = s2; sc[16 + 2 * t + 1] = s3;
            m0 = fminf(m0, fminf(s0, s1));
            m1 = fminf(m1, fminf(s2, s3));
        }

        // per-chunk quad reduce + running min update (off MMA critical path)
        m0 = fminf(m0, __shfl_xor_sync(0xFFFFFFFFu, m0, 1));
        m0 = fminf(m0, __shfl_xor_sync(0xFFFFFFFFu, m0, 2));
        m1 = fminf(m1, __shfl_xor_sync(0xFFFFFFFFu, m1, 1));
        m1 = fminf(m1, __shfl_xor_sync(0xFFFFFFFFu, m1, 2));
        run0 = fminf(run0, m0);
        run1 = fminf(run1, m1);

        // candidate sweep: coarse per-t pair check, rare detailed slow path.
        // Same candidate SET as per-code checks (pair-min < th => re-test each).
        float th0 = run0 + TAU, th1 = run1 + TAU;
        #pragma unroll
        for (int t = 0; t < 8; t++) {
            int code0 = chunk * 64 + t * 8 + (lane & 3) * 2;
            float a0 = sc[2 * t], b0 = sc[2 * t + 1];
            if (fminf(a0, b0) < th0) {
                if (a0 < th0) {
                    unsigned slot = atomicAdd(&sCnt[r0loc], 1u);
                    if (slot < 64) sCand[r0loc * 64 + slot] = (unsigned short)code0;
                }
                if (b0 < th0) {
                    unsigned slot = atomicAdd(&sCnt[r0loc], 1u);
                    if (slot < 64) sCand[r0loc * 64 + slot] = (unsigned short)(code0 + 1);
                }
            }
            float a1 = sc[16 + 2 * t], b1 = sc[16 + 2 * t + 1];
            if (fminf(a1, b1) < th1) {
                if (a1 < th1) {
                    unsigned slot = atomicAdd(&sCnt[r0loc + 8], 1u);
                    if (slot < 64) sCand[(r0loc + 8) * 64 + slot] = (unsigned short)code0;
                }
                if (b1 < th1) {
                    unsigned slot = atomicAdd(&sCnt[r0loc + 8], 1u);
                    if (slot < 64) sCand[(r0loc + 8) * 64 + slot] = (unsigned short)(code0 + 1);
                }
            }
        }
        __syncthreads();         // done reading bufC before restage
    }
    __syncthreads();

    // Rescore: exact fp32 dot per candidate, reference-faithful score,
    // lexicographic (s, k) argmin. Warp w handles rows w, w+4, ...
    for (int rl = wid; rl < 64; rl += 4) {
        int n = rowBase + rl;
        float xn = g_xnorm[n];
        const float* zr = g_zT + (size_t)n * D_EMB;
        float4 za = *(const float4*)(zr + lane * 4);
        float4 zb = *(const float4*)(zr + 128 + lane * 4);

        unsigned cnt = sCnt[rl];
        int num = (cnt <= 64u) ? (int)cnt : K_EMB;
        float best = 1e30f;
        int bestk = K_EMB;
        for (int i = 0; i < num; i++) {
            int k = (cnt <= 64u) ? (int)sCand[rl * 64 + i] : i;
            const float* er = emb + (size_t)k * D_EMB;
            float4 ea = *(const float4*)(er + lane * 4);
            float4 eb4 = *(const float4*)(er + 128 + lane * 4);
            float dot = za.x * ea.x;
            dot = fmaf(za.y, ea.y, dot);
            dot = fmaf(za.z, ea.z, dot);
            dot = fmaf(za.w, ea.w, dot);
            dot = fmaf(zb.x, eb4.x, dot);
            dot = fmaf(zb.y, eb4.y, dot);
            dot = fmaf(zb.z, eb4.z, dot);
            dot = fmaf(zb.w, eb4.w, dot);
            #pragma unroll
            for (int m = 16; m > 0; m >>= 1)
                dot += __shfl_xor_sync(0xFFFFFFFFu, dot, m);
            float s = __fadd_rn(__fadd_rn(xn, sEn[k]), __fmul_rn(-2.0f, dot));
            if (s < best || (s == best && k < bestk)) { best = s; bestk = k; }
        }
        if (lane == 0) {
            sIdx[rl] = bestk;
            out[IDX_OFF + n] = (float)bestk;
            atomicAdd(&g_hist[bestk], 1);
        }
    }
    __syncthreads();

    // Fused gather: z_q in (b,c,dhw) layout + loss partial.
    int b    = rowBase >> 14;
    int dhw0 = rowBase & 16383;
    float lacc = 0.0f;
    for (int h = 0; h < 2; h++) {
        #pragma unroll
        for (int i = 0; i < 16; i++) {
            int nl = wid * 16 + i;
            int n  = rowBase + nl;
            int k  = sIdx[nl];
            float4 e4 = *(const float4*)(emb + (size_t)k * D_EMB + h * 128 + lane * 4);
            float4 z4 = *(const float4*)(g_zT + (size_t)n * D_EMB + h * 128 + lane * 4);
            *(float4*)(sm + SM_A + nl * ROW_PITCH + lane * 16) = e4;
            float dx = z4.x - e4.x, dy = z4.y - e4.y;
            float dz = z4.z - e4.z, dw = z4.w - e4.w;
            lacc += dx * dx + dy * dy + dz * dz + dw * dw;
        }
        __syncthreads();
        #pragma unroll
        for (int ci = 0; ci < 32; ci++) {
            int cl = wid * 32 + ci;
            #pragma unroll
            for (int i2 = 0; i2 < 2; i2++) {
                int nl = i2 * 32 + lane;
                float q = *(const float*)(sm + SM_A + nl * ROW_PITCH + cl * 4);
                out[((size_t)(b * D_EMB + h * 128 + cl)) * DHW + dhw0 + nl] = q;
            }
        }
        __syncthreads();
    }

    // block-reduce loss partial (deterministic tree), reuse sEn region
    float* red = sEn;
    red[tid] = lacc;
    __syncthreads();
    #pragma unroll
    for (int s = 64; s > 0; s >>= 1) {
        if (tid < s) red[tid] += red[tid + s];
        __syncthreads();
    }
    if (tid == 0) g_partial[blockIdx.x] = red[0];
}

// ---------------------------------------------------------------------------
// finalize: vq_loss (deterministic tree over 1024 partials) + perplexity
__global__ void vq_finalize_kernel(float* __restrict__ out) {
    __shared__ float red[1024];
    int t = threadIdx.x;

    red[t] = g_partial[t];
    __syncthreads();
    #pragma unroll
    for (int st = 512; st > 0; st >>= 1) {
        if (t < st) red[t] += red[t + st];
        __syncthreads();
    }
    if (t == 0) out[LOSS_OFF] = 0.25f * red[0] / (float)ZQ_ELEMS;
    __syncthreads();

    float p = (float)g_hist[t] * (1.0f / (float)N_VEC);
    red[t] = p * logf(p + 1e-10f);
    __syncthreads();
    #pragma unroll
    for (int st = 512; st > 0; st >>= 1) {
        if (t < st) red[t] += red[t + st];
        __syncthreads();
    }
    if (t == 0) out[PERP_OFF] = expf(-red[0]);
}

// ---------------------------------------------------------------------------
extern "C" void kernel_launch(void* const* d_in, const int* in_sizes, int n_in,
                              void* d_out, int out_size) {
    const float* z   = (const float*)d_in[0];
    const float* emb = (const float*)d_in[1];
    if (in_sizes[0] == K_EMB * D_EMB) {
        const float* t = z; z = emb; emb = t;
    }
    float* out = (float*)d_out;

    cudaFuncSetAttribute(vq_topk_kernel,
                         cudaFuncAttributeMaxDynamicSharedMemorySize, SM_TOTAL);

    vq_prep_kernel<<<32, 256>>>(emb);                    // launch 1
    vq_xnorm_kernel<<<N_VEC / 256, 256>>>(z);            // launch 2

    dim3 sgrid(N_VEC / 32, D_EMB / 32);
    dim3 sblk(32, 8);
    vq_split_z_kernel<<<sgrid, sblk>>>(z);               // launch 3

    vq_topk_kernel<<<N_VEC / 64, 128, SM_TOTAL>>>(emb, out);   // launch 4 (ncu window)

    vq_finalize_kernel<<<1, 1024>>>(out);                // launch 5
}